// round 17
// baseline (speedup 1.0000x reference)
#include <cuda_runtime.h>
#include <cuda_bf16.h>
#include <math.h>
#include <stdint.h>

#define B_ROWS 16384
#define IN1    256
#define HD     512
#define NB     16
#define NPARTX 1024          // partials for x stats
#define NPARTH 128           // partials for h stats (= GEMM grid.y)
#define K1     (IN1 * NB)    // 4096
#define K2     (HD * NB)     // 8192

// GEMM: CTA 128x128, 8 warps (2x4), warp tile 64x32, BK=64
#define BM 128
#define BN 128
#define BK 64
#define AB_BYTES   32768
#define AB_LO      16384
#define B_BASE     65536
#define B_STAGE    32768
#define B_LO       16384
#define SRC_BASE   (B_BASE + 3 * B_STAGE)    // 163840
#define SRC_SLOT   2048
#define STAT_BASE  (SRC_BASE + 3 * SRC_SLOT) // 169984  (2x128 floats s + q)
#define GEMM_SMEM  (STAT_BASE + 4096)        // 174080

// ---------------- scratch (device globals) -----------------------------------
__device__ float g_mu1[IN1], g_inv1[IN1];
__device__ float g_mu2[HD],  g_inv2[HD];
__device__ float g_mu3[HD],  g_inv3[HD];
__device__ float g_ps[NPARTX * HD];
__device__ float g_pq[NPARTX * HD];
__device__ __align__(128) __nv_bfloat16 g_cb1h[(size_t)HD * K1];
__device__ __align__(128) __nv_bfloat16 g_cb1l[(size_t)HD * K1];
__device__ __align__(128) __nv_bfloat16 g_cb2h[(size_t)HD * K2];
__device__ __align__(128) __nv_bfloat16 g_cb2l[(size_t)HD * K2];
__device__ float  g_h1[(size_t)B_ROWS * HD];
__device__ float  g_h2[(size_t)B_ROWS * HD];
__device__ float  g_cp3[HD * NB];

// ---------------- PTX helpers --------------------------------------------------
__device__ __forceinline__ uint32_t smem_u32(const void* p) {
    uint32_t a;
    asm("{ .reg .u64 t; cvta.to.shared.u64 t, %1; cvt.u32.u64 %0, t; }" : "=r"(a) : "l"(p));
    return a;
}
__device__ __forceinline__ uint32_t sw128(uint32_t b) { return b ^ ((b >> 3) & 0x70u); }
__device__ __forceinline__ void cp16(uint32_t s, const void* g) {
    asm volatile("cp.async.cg.shared.global [%0], [%1], 16;" :: "r"(s), "l"(g));
}
#define CP_COMMIT() asm volatile("cp.async.commit_group;" ::: "memory")

__device__ __forceinline__ void ldmx4(uint32_t* r, uint32_t addr) {
    asm volatile("ldmatrix.sync.aligned.m8n8.x4.shared.b16 {%0,%1,%2,%3}, [%4];"
        : "=r"(r[0]), "=r"(r[1]), "=r"(r[2]), "=r"(r[3]) : "r"(addr));
}
// bf16 operands, fp32 accumulate — PROVEN precision path (rel_err ~1e-4)
__device__ __forceinline__ void mma_f32(float* c, const uint32_t* a, const uint32_t* b) {
    asm("mma.sync.aligned.m16n8k16.row.col.f32.bf16.bf16.f32 "
        "{%0,%1,%2,%3}, {%4,%5,%6,%7}, {%8,%9}, {%0,%1,%2,%3};"
        : "+f"(c[0]), "+f"(c[1]), "+f"(c[2]), "+f"(c[3])
        : "r"(a[0]), "r"(a[1]), "r"(a[2]), "r"(a[3]), "r"(b[0]), "r"(b[1]));
}
// packs (lo, hi) floats into bf16x2 word, lo at low half (RN)
__device__ __forceinline__ uint32_t bf16pack(float lo, float hi) {
    uint32_t w;
    asm("cvt.rn.bf16x2.f32 %0, %1, %2;" : "=r"(w) : "f"(hi), "f"(lo));
    return w;
}

// ---------------- stats core ----------------------------------------------------
__device__ __forceinline__ void stats_part_body(const float* __restrict__ src, int C,
                                                int bid, int tid) {
    const int rows = B_ROWS / NPARTX;   // 16
    const int r0 = bid * rows;
    float s = 0.f, q = 0.f;
    for (int rr = 0; rr < rows; rr++) {
        float v = src[(size_t)(r0 + rr) * C + tid];
        s += v;
        q = fmaf(v, v, q);
    }
    g_ps[bid * C + tid] = s;
    g_pq[bid * C + tid] = q;
}

// one block per column, 128 threads: stride-P partial sums + tree reduce
__global__ void k_stats_fin(int C, int P, float* __restrict__ mu, float* __restrict__ inv) {
    int c = blockIdx.x;
    int t = threadIdx.x, lane = t & 31, wrp = t >> 5;
    float s = 0.f, q = 0.f;
    for (int k = t; k < P; k += 128) { s += g_ps[k * C + c]; q += g_pq[k * C + c]; }
#pragma unroll
    for (int off = 16; off; off >>= 1) {
        s += __shfl_xor_sync(0xffffffffu, s, off);
        q += __shfl_xor_sync(0xffffffffu, q, off);
    }
    __shared__ float ss[4], qq[4];
    if (lane == 0) { ss[wrp] = s; qq[wrp] = q; }
    __syncthreads();
    if (t == 0) {
        float S = ss[0] + ss[1] + ss[2] + ss[3];
        float Q = qq[0] + qq[1] + qq[2] + qq[3];
        float m = S / (float)B_ROWS;
        float var = (Q - S * m) / (float)(B_ROWS - 1);
        float sd = sqrtf(fmaxf(var, 0.f));
        mu[c] = m;
        inv[c] = 1.f / (sd + 1e-6f);
    }
}

// ---------------- coeff split (bf16 hi/lo, Kn folded) ----------------------------
__device__ __forceinline__ void coeff_split_body(const float* __restrict__ src, int K,
        __nv_bfloat16* __restrict__ Bh, __nv_bfloat16* __restrict__ Bl, int o, int tid) {
    for (int k = tid; k < K; k += 256) {
        int n = k & 15;
        float cn = fmaf((float)n, 4.f / 15.f, -2.f);
        float Kn = expf(-2.f * cn * cn);
        float v = src[(size_t)o * K + k] * Kn;
        __nv_bfloat16 h = __float2bfloat16(v);
        Bh[(size_t)o * K + k] = h;
        Bl[(size_t)o * K + k] = __float2bfloat16(v - __bfloat162float(h));
    }
}

// fused: stats_part(x) + coeff_split(c1) + coeffs3  (c2 split moved into GEMM1 grid)
__global__ void k_prep0(const float* __restrict__ x, const float* __restrict__ c1,
                        const float* __restrict__ c3,
                        __nv_bfloat16* __restrict__ cb1h, __nv_bfloat16* __restrict__ cb1l,
                        float* __restrict__ cp3) {
    int bid = blockIdx.x, tid = threadIdx.x;
    if (bid < NPARTX) {
        stats_part_body(x, IN1, bid, tid);
    } else if (bid < NPARTX + HD) {
        coeff_split_body(c1, K1, cb1h, cb1l, bid - NPARTX, tid);
    } else {
        for (int w = tid; w < HD * NB; w += 256) {
            int i = w >> 4, j = w & 15;
            int n = 15 - j;
            float cn = fmaf((float)n, 4.f / 15.f, -2.f);
            float Kn = expf(-2.f * cn * cn);
            cp3[i * NB + j] = c3[(size_t)i * NB + n] * Kn;
        }
    }
}

// ---------------- fused basis-gen + split-bf16 GEMM + tanh + stats ---------------
__device__ __forceinline__ void load_B(uint32_t stage_base,
        const __nv_bfloat16* __restrict__ Bh, const __nv_bfloat16* __restrict__ Bl,
        int on0, int k0, int K, int tid) {
#pragma unroll
    for (int q = 0; q < 4; q++) {
        int e = tid + (q << 8);
        int row = e >> 3, ch = e & 7;
        uint32_t so = sw128((uint32_t)(row << 7) + (ch << 4));
        size_t gb = (size_t)(on0 + row) * K + k0 + (ch << 3);
        cp16(stage_base + so, Bh + gb);
        cp16(stage_base + B_LO + so, Bl + gb);
    }
}

__device__ __forceinline__ void gen_pair(char* smem, int p, uint32_t src_slot,
        uint32_t abuf, int i0, const float* __restrict__ mu,
        const float* __restrict__ inv) {
    int row = p >> 2, icol = p & 3;
    float v = reinterpret_cast<const float*>(smem + SRC_BASE + src_slot * SRC_SLOT)
                  [(row << 2) + icol];
    int i = i0 + icol;
    float xn = (v - __ldg(mu + i)) * __ldg(inv + i);
    xn = fminf(3.f, fmaxf(-3.f, xn));
    float t = __expf(fmaf(-2.f * xn, xn, -8.f * xn));
    float r = __expf(xn * (16.f / 15.f));
    uint32_t wh[8], wl[8];
    float pv = t;
#pragma unroll
    for (int m = 0; m < 8; m++) {
        float p0 = pv;
        float p1 = pv * r;
        pv = p1 * r;
        uint32_t w = bf16pack(p0, p1);
        wh[m] = w;
        float h0 = __uint_as_float(w << 16);
        float h1 = __uint_as_float(w & 0xffff0000u);
        wl[m] = bf16pack(p0 - h0, p1 - h1);
    }
    uint32_t base = (uint32_t)(row << 7) + (icol << 5);
    uint32_t a0 = sw128(base), a1 = sw128(base + 16);
    *reinterpret_cast<uint4*>(smem + abuf + a0) = make_uint4(wh[0], wh[1], wh[2], wh[3]);
    *reinterpret_cast<uint4*>(smem + abuf + a1) = make_uint4(wh[4], wh[5], wh[6], wh[7]);
    *reinterpret_cast<uint4*>(smem + abuf + AB_LO + a0) = make_uint4(wl[0], wl[1], wl[2], wl[3]);
    *reinterpret_cast<uint4*>(smem + abuf + AB_LO + a1) = make_uint4(wl[4], wl[5], wl[6], wl[7]);
}

// GEMM blocks: blockIdx.x < nx.  Extra blocks (blockIdx.x >= nx) run the c2
// coeff split concurrently — GEMM1's DRAM is idle (0.6%), so this traffic hides.
__global__ void __launch_bounds__(256, 1)
k_gemm(const float* __restrict__ src, const float* __restrict__ mu,
       const float* __restrict__ inv,
       const __nv_bfloat16* __restrict__ Bh, const __nv_bfloat16* __restrict__ Bl,
       float* __restrict__ out, int K, int C, int nx,
       const float* __restrict__ sc_src,
       __nv_bfloat16* __restrict__ sc_h, __nv_bfloat16* __restrict__ sc_l) {
    if ((int)blockIdx.x >= nx) {
        // side-channel: split c2 for the NEXT layer (independent of this GEMM)
        int o = (blockIdx.x - nx) * (int)gridDim.y + blockIdx.y;
        coeff_split_body(sc_src, K2, sc_h, sc_l, o, threadIdx.x);
        return;
    }

    extern __shared__ __align__(1024) char smem_raw[];
    const uint32_t base = smem_u32(smem_raw);
    const int tid = threadIdx.x;
    const int lane = tid & 31, wid = tid >> 5;
    const int wr = wid & 1, wc = wid >> 1;
    const int bm0 = blockIdx.y << 7, on0 = blockIdx.x << 7;
    const int NCH = K >> 6;

    float acc[4][4][4];
#pragma unroll
    for (int mt = 0; mt < 4; mt++)
#pragma unroll
        for (int nt = 0; nt < 4; nt++)
#pragma unroll
            for (int e = 0; e < 4; e++) acc[mt][nt][e] = 0.f;

    load_B(base + B_BASE, Bh, Bl, on0, 0, K, tid);
    if (tid < 128) cp16(base + SRC_BASE + (tid << 4),
                        src + (size_t)(bm0 + tid) * C);
    CP_COMMIT();
    load_B(base + B_BASE + B_STAGE, Bh, Bl, on0, BK, K, tid);
    if (tid < 128) cp16(base + SRC_BASE + SRC_SLOT + (tid << 4),
                        src + (size_t)(bm0 + tid) * C + 4);
    CP_COMMIT();
    asm volatile("cp.async.wait_group 1;" ::: "memory");
    __syncthreads();
    gen_pair(smem_raw, tid * 2,     0, 0, 0, mu, inv);
    gen_pair(smem_raw, tid * 2 + 1, 0, 0, 0, mu, inv);

    const int g = lane >> 3, lr = lane & 7;

    for (int c = 0; c < NCH; c++) {
        asm volatile("cp.async.wait_group 0;" ::: "memory");
        __syncthreads();

        if (c + 2 < NCH) {
            int s = (c + 2) % 3;
            load_B(base + B_BASE + (uint32_t)s * B_STAGE, Bh, Bl, on0, (c + 2) << 6, K, tid);
            if (tid < 128) cp16(base + SRC_BASE + (uint32_t)s * SRC_SLOT + (tid << 4),
                                src + (size_t)(bm0 + tid) * C + ((c + 2) << 2));
            CP_COMMIT();
        }

        const uint32_t abuf = (uint32_t)(c & 1) * AB_BYTES;
        const uint32_t bst  = B_BASE + (uint32_t)(c % 3) * B_STAGE;
        const bool do_gen = (c + 1 < NCH);
        const uint32_t gslot = (uint32_t)((c + 1) % 3);
        const uint32_t gbuf = (uint32_t)((c + 1) & 1) * AB_BYTES;
        const int gi0 = (c + 1) << 2;

#pragma unroll
        for (int kk = 0; kk < 4; kk++) {
            uint32_t afh[4][4], afl[4][4];
#pragma unroll
            for (int mt = 0; mt < 4; mt++) {
                int m_local = wr * 64 + mt * 16 + (g & 1) * 8 + lr;
                uint32_t off = sw128((uint32_t)(m_local << 7) + (kk << 5) + ((g >> 1) << 4));
                ldmx4(afh[mt], base + abuf + off);
                ldmx4(afl[mt], base + abuf + AB_LO + off);
            }
            uint32_t bfh[2][4], bfl[2][4];
#pragma unroll
            for (int n2 = 0; n2 < 2; n2++) {
                int n_local = wc * 32 + n2 * 16 + (g >> 1) * 8 + lr;
                uint32_t off = sw128((uint32_t)(n_local << 7) + (kk << 5) + ((g & 1) << 4));
                ldmx4(bfh[n2], base + bst + off);
                ldmx4(bfl[n2], base + bst + B_LO + off);
            }
            // term-major: per-acc order preserved (hi*Bh, hi*Bl, lo*Bh), fp32 acc
#pragma unroll
            for (int term = 0; term < 3; term++)
#pragma unroll
                for (int mt = 0; mt < 4; mt++)
#pragma unroll
                    for (int nt = 0; nt < 4; nt++) {
                        const uint32_t* A = (term == 2) ? afl[mt] : afh[mt];
                        const uint32_t* B = (term == 1)
                            ? &bfl[nt >> 1][(nt & 1) * 2]
                            : &bfh[nt >> 1][(nt & 1) * 2];
                        mma_f32(acc[mt][nt], A, B);
                    }

            if (kk == 1 && do_gen) gen_pair(smem_raw, tid * 2,     gslot, gbuf, gi0, mu, inv);
            if (kk == 3 && do_gen) gen_pair(smem_raw, tid * 2 + 1, gslot, gbuf, gi0, mu, inv);
        }
    }

    // epilogue: tanh + store + column-stats partials
    float s_e[4][2], q_e[4][2];
#pragma unroll
    for (int nt = 0; nt < 4; nt++) { s_e[nt][0] = s_e[nt][1] = 0.f; q_e[nt][0] = q_e[nt][1] = 0.f; }

#pragma unroll
    for (int mt = 0; mt < 4; mt++) {
        int row0 = bm0 + wr * 64 + mt * 16 + (lane >> 2);
#pragma unroll
        for (int nt = 0; nt < 4; nt++) {
            int col = on0 + wc * 32 + nt * 8 + (lane & 3) * 2;
            float2 v0, v1;
            v0.x = tanhf(acc[mt][nt][0]);
            v0.y = tanhf(acc[mt][nt][1]);
            v1.x = tanhf(acc[mt][nt][2]);
            v1.y = tanhf(acc[mt][nt][3]);
            *reinterpret_cast<float2*>(out + (size_t)row0 * HD + col) = v0;
            *reinterpret_cast<float2*>(out + (size_t)(row0 + 8) * HD + col) = v1;
            s_e[nt][0] += v0.x + v1.x;  s_e[nt][1] += v0.y + v1.y;
            q_e[nt][0] += v0.x * v0.x + v1.x * v1.x;
            q_e[nt][1] += v0.y * v0.y + v1.y * v1.y;
        }
    }
    float* s_buf = reinterpret_cast<float*>(smem_raw + STAT_BASE);          // [2][128]
    float* q_buf = reinterpret_cast<float*>(smem_raw + STAT_BASE + 1024);   // [2][128]
#pragma unroll
    for (int nt = 0; nt < 4; nt++)
#pragma unroll
        for (int j = 0; j < 2; j++) {
            float s = s_e[nt][j], q = q_e[nt][j];
#pragma unroll
            for (int off = 4; off < 32; off <<= 1) {
                s += __shfl_xor_sync(0xffffffffu, s, off);
                q += __shfl_xor_sync(0xffffffffu, q, off);
            }
            if (lane < 4) {
                int colL = wc * 32 + nt * 8 + lane * 2 + j;
                s_buf[wr * 128 + colL] = s;
                q_buf[wr * 128 + colL] = q;
            }
        }
    __syncthreads();
    if (tid < 128) {
        g_ps[blockIdx.y * HD + on0 + tid] = s_buf[tid] + s_buf[128 + tid];
        g_pq[blockIdx.y * HD + on0 + tid] = q_buf[tid] + q_buf[128 + tid];
    }
}

// ---------------- final layer: t,r inline + Horner + skip ------------------------
__global__ void k_final(const float* __restrict__ h2, const float* __restrict__ mu,
                        const float* __restrict__ inv, const float* __restrict__ cp3,
                        const float* __restrict__ x, const float* __restrict__ sw,
                        const float* __restrict__ sb, float* __restrict__ out) {
    int warp = threadIdx.x >> 5, lane = threadIdx.x & 31;
    int b = blockIdx.x * 8 + warp;
    float acc = 0.f;
    for (int i = lane; i < HD; i += 32) {
        float xn = (h2[(size_t)b * HD + i] - mu[i]) * inv[i];
        xn = fminf(3.f, fmaxf(-3.f, xn));
        float t = __expf(fmaf(-2.f * xn, xn, -8.f * xn));
        float r = __expf(xn * (16.f / 15.f));
        const float* c = &cp3[i * NB];
        float p = c[0];
#pragma unroll
        for (int j = 1; j < NB; j++) p = fmaf(p, r, c[j]);
        acc = fmaf(t, p, acc);
    }
    for (int cidx = lane; cidx < IN1; cidx += 32)
        acc = fmaf(x[(size_t)b * IN1 + cidx], sw[cidx], acc);
#pragma unroll
    for (int off = 16; off; off >>= 1) acc += __shfl_xor_sync(0xffffffffu, acc, off);
    if (lane == 0) out[b] = acc + sb[0];
}

// ---------------- launch ---------------------------------------------------------
extern "C" void kernel_launch(void* const* d_in, const int* in_sizes, int n_in,
                              void* d_out, int out_size) {
    const float* x  = (const float*)d_in[0];
    const float* c1 = (const float*)d_in[1];
    const float* c2 = (const float*)d_in[2];
    const float* c3 = (const float*)d_in[3];
    const float* sw = (const float*)d_in[4];
    const float* sb = (const float*)d_in[5];
    float* out = (float*)d_out;

    __nv_bfloat16 *cb1h, *cb1l, *cb2h, *cb2l;
    float *h1, *h2, *cp3, *mu1, *inv1, *mu2, *inv2, *mu3, *inv3;
    cudaGetSymbolAddress((void**)&cb1h, g_cb1h);
    cudaGetSymbolAddress((void**)&cb1l, g_cb1l);
    cudaGetSymbolAddress((void**)&cb2h, g_cb2h);
    cudaGetSymbolAddress((void**)&cb2l, g_cb2l);
    cudaGetSymbolAddress((void**)&h1,   g_h1);
    cudaGetSymbolAddress((void**)&h2,   g_h2);
    cudaGetSymbolAddress((void**)&cp3,  g_cp3);
    cudaGetSymbolAddress((void**)&mu1,  g_mu1);
    cudaGetSymbolAddress((void**)&inv1, g_inv1);
    cudaGetSymbolAddress((void**)&mu2,  g_mu2);
    cudaGetSymbolAddress((void**)&inv2, g_inv2);
    cudaGetSymbolAddress((void**)&mu3,  g_mu3);
    cudaGetSymbolAddress((void**)&inv3, g_inv3);

    cudaFuncSetAttribute(k_gemm, cudaFuncAttributeMaxDynamicSharedMemorySize, GEMM_SMEM);

    // 0: fused stats(x) + c1 split + c3 transform (c2 split rides in GEMM1)
    k_prep0<<<NPARTX + HD + 1, 256>>>(x, c1, c3, cb1h, cb1l, cp3);
    // 1: parallel stats_fin(x)
    k_stats_fin<<<IN1, 128>>>(IN1, NPARTX, mu1, inv1);
    // 2: GEMM layer 1 + side-channel c2 split (extra 4x128 blocks)
    k_gemm<<<dim3(HD / BN + 4, B_ROWS / BM), 256, GEMM_SMEM>>>(
        x, mu1, inv1, cb1h, cb1l, h1, K1, IN1, HD / BN, c2, cb2h, cb2l);
    k_stats_fin<<<HD, 128>>>(HD, NPARTH, mu2, inv2);
    // layer 2 (no side-channel)
    k_gemm<<<dim3(HD / BN, B_ROWS / BM), 256, GEMM_SMEM>>>(
        h1, mu2, inv2, cb2h, cb2l, h2, K2, HD, HD / BN, nullptr, nullptr, nullptr);
    k_stats_fin<<<HD, 128>>>(HD, NPARTH, mu3, inv3);
    // layer 3 + skip
    k_final<<<B_ROWS / 8, 256>>>(h2, mu3, inv3, cp3, x, sw, sb, out);
}